// round 15
// baseline (speedup 1.0000x reference)
#include <cuda_runtime.h>
#include <cuda_fp16.h>
#include <cuda_bf16.h>

// GCN: 3x (h = relu(A_norm @ (h @ W) + b)) -> global mean pool -> MLP.
// ALGEBRA: out[d] = dinv[d] * ( sum_e hhat[src_e] + hhat[d] ),
//          hhat[r] = dinv[r] * (h @ W)[r]  (prescaled in GEMM epilogue)
// -> no per-edge norms; scatter stores only 4B src indices.
// 9 launches: hist(+rank), scan(spin-fused), scatter+gemm1(fused ranges),
// agg1, gemm2, agg2, gemm3, agg3, pool+mlp.
// AGGREGATE v6: PERSISTENT (888 blocks = 1 wave, no CTA churn) and each warp
// interleaves TWO nodes' edge streams -> 2x independent outstanding gathers.
// hhat fp16 (128B/row), fp32 accumulate. No float atomics anywhere.

#define NMAX 50000
#define EMAX 800000
#define SCAN_B 1024
#define NB_MAX 64

__device__ __half2 g_hW16[NMAX * 32];  // dinv-prescaled GEMM out (agg input)
__device__ float2  g_h2[NMAX * 32];    // activations (agg out, GEMM in)
__device__ float   g_dinv[NMAX];
__device__ int     g_deg[NMAX];        // re-zeroed every run
__device__ int     g_rowptr[NMAX + 1];
__device__ int     g_rank[EMAX];       // per-edge rank from hist
__device__ int     g_esrc[EMAX];       // CSR edge sources (4B records)
__device__ int     g_bsum[NB_MAX];
__device__ int     g_tick1, g_tick2;   // scan tickets (self-resetting)

// ---------------------------------------------------------------------------
// Histogram of dst; atomic return value = edge rank (stored coalesced).
__global__ void hist_kernel(const int* __restrict__ ei, int E) {
    int base = (blockIdx.x * blockDim.x + threadIdx.x) * 4;
    if ((E & 3) == 0) {
        if (base < E) {
            int4 d = *reinterpret_cast<const int4*>(ei + E + base);
            int4 r;
            r.x = atomicAdd(&g_deg[d.x], 1);
            r.y = atomicAdd(&g_deg[d.y], 1);
            r.z = atomicAdd(&g_deg[d.z], 1);
            r.w = atomicAdd(&g_deg[d.w], 1);
            *reinterpret_cast<int4*>(g_rank + base) = r;
        }
    } else {
#pragma unroll
        for (int j = 0; j < 4; j++)
            if (base + j < E)
                g_rank[base + j] = atomicAdd(&g_deg[ei[E + base + j]], 1);
    }
}

// Spin-fused scan (all nb<=49 blocks resident): reduce -> spin -> prefix ->
// rowptr/dinv, zero deg. Tickets self-reset for graph replay.
__global__ void scan_kernel(int n, int nb) {
    __shared__ int ws[32];
    __shared__ int blockoff;
    const int lane = threadIdx.x & 31, wid = threadIdx.x >> 5;
    int idx = blockIdx.x * SCAN_B + threadIdx.x;
    int v = (idx < n) ? g_deg[idx] : 0;
    int sc = v;
#pragma unroll
    for (int off = 1; off < 32; off <<= 1) {
        int u = __shfl_up_sync(0xffffffffu, sc, off);
        if (lane >= off) sc += u;
    }
    if (lane == 31) ws[wid] = sc;
    __syncthreads();
    if (wid == 0) {
        int s = ws[lane];
#pragma unroll
        for (int off = 1; off < 32; off <<= 1) {
            int u = __shfl_up_sync(0xffffffffu, s, off);
            if (lane >= off) s += u;
        }
        ws[lane] = s;
    }
    __syncthreads();
    if (threadIdx.x == 0) {
        g_bsum[blockIdx.x] = ws[31];
        __threadfence();
        atomicAdd(&g_tick1, 1);
        while (*((volatile int*)&g_tick1) < nb) {}
        int run = 0;
        for (int j = 0; j < blockIdx.x; j++)
            run += ((volatile int*)g_bsum)[j];
        blockoff = run;
    }
    __syncthreads();
    int ex = blockoff + (wid ? ws[wid - 1] : 0) + sc - v;
    if (idx < n) {
        g_rowptr[idx] = ex;
        g_dinv[idx] = rsqrtf((float)(v + 1));   // +1 self loop
        g_deg[idx] = 0;
        if (idx == n - 1) g_rowptr[n] = ex + v;
    }
    __syncthreads();
    if (threadIdx.x == 0) {
        int t = atomicAdd(&g_tick2, 1);
        if (t == nb - 1) { g_tick1 = 0; g_tick2 = 0; __threadfence(); }
    }
}

// Fused: blocks [0,scatB) scatter (4B store, atomic-free); rest do layer-1
// GEMM with dinv prescale. Both depend only on scan; fully independent.
__global__ void scatter_gemm1_kernel(const int* __restrict__ ei, int E,
                                     const float* __restrict__ X,
                                     const float* __restrict__ W, int n,
                                     int scatB) {
    if (blockIdx.x < scatB) {
        int base = (blockIdx.x * blockDim.x + threadIdx.x) * 4;
        if ((E & 3) == 0) {
            if (base < E) {
                int4 s4 = *reinterpret_cast<const int4*>(ei + base);
                int4 d4 = *reinterpret_cast<const int4*>(ei + E + base);
                int4 r4 = *reinterpret_cast<const int4*>(g_rank + base);
                g_esrc[g_rowptr[d4.x] + r4.x] = s4.x;
                g_esrc[g_rowptr[d4.y] + r4.y] = s4.y;
                g_esrc[g_rowptr[d4.z] + r4.z] = s4.z;
                g_esrc[g_rowptr[d4.w] + r4.w] = s4.w;
            }
        } else {
#pragma unroll
            for (int j = 0; j < 4; j++) {
                if (base + j < E) {
                    int s = ei[base + j], d = ei[E + base + j];
                    g_esrc[g_rowptr[d] + g_rank[base + j]] = s;
                }
            }
        }
        return;
    }
    // --- gemm1: hhat = fp16(dinv[row] * (X @ W1)[row]) ---
    __shared__ float2 Ws[32 * 32];   // Ws[k*32+l] = (W[k][2l], W[k][2l+1])
    for (int i = threadIdx.x; i < 32 * 32; i += blockDim.x)
        Ws[i] = reinterpret_cast<const float2*>(W)[i];
    __syncthreads();
    const int lane = threadIdx.x & 31;
    const int warp = ((blockIdx.x - scatB) * blockDim.x + threadIdx.x) >> 5;
    const int nwarps = ((gridDim.x - scatB) * blockDim.x) >> 5;
    for (int row = warp; row < n; row += nwarps) {
        float x0 = X[(unsigned)row * 32u + lane];
        float ax = 0.f, ay = 0.f;
#pragma unroll
        for (int k = 0; k < 32; k++) {
            float xv = __shfl_sync(0xffffffffu, x0, k);
            float2 w = Ws[k * 32 + lane];
            ax += xv * w.x; ay += xv * w.y;
        }
        float dn = g_dinv[row];
        g_hW16[(unsigned)row * 32u + lane] =
            __floats2half2_rn(ax * dn, ay * dn);
    }
}

// ---------------------------------------------------------------------------
// Mid-layer GEMM: hhat = fp16(dinv[row] * (g_h2[row] @ W)). Warp-per-row.
__global__ void gemm64_kernel(const float* __restrict__ W, int n) {
    __shared__ float2 Ws[64 * 32];
    for (int i = threadIdx.x; i < 64 * 32; i += blockDim.x)
        Ws[i] = reinterpret_cast<const float2*>(W)[i];
    __syncthreads();
    const int lane = threadIdx.x & 31;
    const int warp = (blockIdx.x * blockDim.x + threadIdx.x) >> 5;
    const int nwarps = (gridDim.x * blockDim.x) >> 5;
    for (int row = warp; row < n; row += nwarps) {
        float2 xr = g_h2[(unsigned)row * 32u + lane];
        float ax = 0.f, ay = 0.f;
#pragma unroll
        for (int k = 0; k < 32; k++) {
            float xk0 = __shfl_sync(0xffffffffu, xr.x, k);
            float xk1 = __shfl_sync(0xffffffffu, xr.y, k);
            float2 w0 = Ws[(2 * k) * 32 + lane];
            float2 w1 = Ws[(2 * k + 1) * 32 + lane];
            ax += xk0 * w0.x + xk1 * w1.x;
            ay += xk0 * w0.y + xk1 * w1.y;
        }
        float dn = g_dinv[row];
        g_hW16[(unsigned)row * 32u + lane] =
            __floats2half2_rn(ax * dn, ay * dn);
    }
}

// ---------------------------------------------------------------------------
__device__ __forceinline__ float2 hload(int src, int lane) {
    return __half22float2(g_hW16[(unsigned)src * 32u + lane]);
}

// PERSISTENT dual-node aggregation: one CTA wave (no churn); each warp
// interleaves two nodes' edge streams (2 edges each per iteration) for 2x
// independent gathers in flight. out = relu(dinv*acc + b).
__global__ void aggregate_kernel(const float* __restrict__ b, int n) {
    const int lane = threadIdx.x & 31;
    const int gwarp = (blockIdx.x * blockDim.x + threadIdx.x) >> 5;
    const int nwarps = (gridDim.x * blockDim.x) >> 5;
    float2 bb = reinterpret_cast<const float2*>(b)[lane];
    for (int na = gwarp * 2; na < n; na += nwarps * 2) {
        const int nb_ = na + 1;
        const bool hasB = nb_ < n;
        float2 svA = hload(na, lane);
        float axA = svA.x, ayA = svA.y;
        float axB = 0.f, ayB = 0.f;
        int pa = g_rowptr[na];
        const int ea = g_rowptr[na + 1];
        int pb = ea;                            // rowptr[nb_] == rowptr[na+1]
        int eb = ea;
        if (hasB) {
            float2 svB = hload(nb_, lane);
            axB = svB.x; ayB = svB.y;
            eb = g_rowptr[nb_ + 1];
        }
        // interleaved main loop: 2 edges from A + 2 edges from B
        while (pa + 1 < ea && pb + 1 < eb) {
            int sa0 = g_esrc[pa], sa1 = g_esrc[pa + 1];
            int sb0 = g_esrc[pb], sb1 = g_esrc[pb + 1];
            float2 va0 = hload(sa0, lane);
            float2 va1 = hload(sa1, lane);
            float2 vb0 = hload(sb0, lane);
            float2 vb1 = hload(sb1, lane);
            axA += va0.x + va1.x; ayA += va0.y + va1.y;
            axB += vb0.x + vb1.x; ayB += vb0.y + vb1.y;
            pa += 2; pb += 2;
        }
        // drain A (4-deep)
        while (pa + 3 < ea) {
            int s0 = g_esrc[pa], s1 = g_esrc[pa + 1];
            int s2 = g_esrc[pa + 2], s3 = g_esrc[pa + 3];
            float2 v0 = hload(s0, lane), v1 = hload(s1, lane);
            float2 v2 = hload(s2, lane), v3 = hload(s3, lane);
            axA += v0.x + v1.x + v2.x + v3.x;
            ayA += v0.y + v1.y + v2.y + v3.y;
            pa += 4;
        }
        while (pa < ea) {
            float2 v = hload(g_esrc[pa], lane);
            axA += v.x; ayA += v.y; pa++;
        }
        // drain B (4-deep)
        while (pb + 3 < eb) {
            int s0 = g_esrc[pb], s1 = g_esrc[pb + 1];
            int s2 = g_esrc[pb + 2], s3 = g_esrc[pb + 3];
            float2 v0 = hload(s0, lane), v1 = hload(s1, lane);
            float2 v2 = hload(s2, lane), v3 = hload(s3, lane);
            axB += v0.x + v1.x + v2.x + v3.x;
            ayB += v0.y + v1.y + v2.y + v3.y;
            pb += 4;
        }
        while (pb < eb) {
            float2 v = hload(g_esrc[pb], lane);
            axB += v.x; ayB += v.y; pb++;
        }
        float dnA = g_dinv[na];
        g_h2[(unsigned)na * 32u + lane] =
            make_float2(fmaxf(dnA * axA + bb.x, 0.f),
                        fmaxf(dnA * ayA + bb.y, 0.f));
        if (hasB) {
            float dnB = g_dinv[nb_];
            g_h2[(unsigned)nb_ * 32u + lane] =
                make_float2(fmaxf(dnB * axB + bb.x, 0.f),
                            fmaxf(dnB * ayB + bb.y, 0.f));
        }
    }
}

// ---------------------------------------------------------------------------
__device__ __forceinline__ int lbound(const int* __restrict__ a, int n, int v) {
    int lo = 0, hi = n;
    while (lo < hi) {
        int m = (lo + hi) >> 1;
        if (a[m] < v) lo = m + 1; else hi = m;
    }
    return lo;
}

// Fused mean-pool + MLP head. One warp per graph (batch ids sorted).
__global__ void pool_mlp_kernel(const int* __restrict__ batch,
                                const float* __restrict__ lw1,
                                const float* __restrict__ lb1,
                                const float* __restrict__ lw2,
                                const float* __restrict__ lb2,
                                float* __restrict__ out, int n, int G) {
    __shared__ float2 Ws[64 * 32];
    for (int i = threadIdx.x; i < 64 * 32; i += blockDim.x)
        Ws[i] = reinterpret_cast<const float2*>(lw1)[i];
    __syncthreads();
    const int lane = threadIdx.x & 31;
    const int g = (blockIdx.x * blockDim.x + threadIdx.x) >> 5;
    if (g >= G) return;
    int start = lbound(batch, n, g);
    int end   = lbound(batch, n, g + 1);
    float px = 0.f, py = 0.f;
    for (int i = start; i < end; i++) {
        float2 v = g_h2[(unsigned)i * 32u + lane];
        px += v.x; py += v.y;
    }
    int cnt = end - start;
    float inv = 1.f / (float)(cnt > 0 ? cnt : 1);
    px *= inv; py *= inv;

    float2 lb = reinterpret_cast<const float2*>(lb1)[lane];
    float ax = lb.x, ay = lb.y;
#pragma unroll
    for (int k = 0; k < 32; k++) {
        float pk0 = __shfl_sync(0xffffffffu, px, k);
        float pk1 = __shfl_sync(0xffffffffu, py, k);
        float2 w0 = Ws[(2 * k) * 32 + lane];
        float2 w1 = Ws[(2 * k + 1) * 32 + lane];
        ax += pk0 * w0.x + pk1 * w1.x;
        ay += pk0 * w0.y + pk1 * w1.y;
    }
    ax = fmaxf(ax, 0.f);
    ay = fmaxf(ay, 0.f);
    float4 w2 = reinterpret_cast<const float4*>(lw2)[lane];
    float o0 = ax * w2.x + ay * w2.z;
    float o1 = ax * w2.y + ay * w2.w;
#pragma unroll
    for (int off = 16; off; off >>= 1) {
        o0 += __shfl_down_sync(0xffffffffu, o0, off);
        o1 += __shfl_down_sync(0xffffffffu, o1, off);
    }
    if (lane == 0) {
        out[g * 2 + 0] = o0 + lb2[0];
        out[g * 2 + 1] = o1 + lb2[1];
    }
}

// ---------------------------------------------------------------------------
extern "C" void kernel_launch(void* const* d_in, const int* in_sizes, int n_in,
                              void* d_out, int out_size) {
    const float* x     = (const float*)d_in[0];
    const int*   ei    = (const int*)d_in[1];    // int64 ref -> int32 device
    const int*   batch = (const int*)d_in[2];
    const float* W1 = (const float*)d_in[3];
    const float* b1 = (const float*)d_in[4];
    const float* W2 = (const float*)d_in[5];
    const float* b2 = (const float*)d_in[6];
    const float* W3 = (const float*)d_in[7];
    const float* b3 = (const float*)d_in[8];
    const float* lw1 = (const float*)d_in[9];
    const float* lb1 = (const float*)d_in[10];
    const float* lw2 = (const float*)d_in[11];
    const float* lb2 = (const float*)d_in[12];
    float* out = (float*)d_out;

    const int N = in_sizes[0] / 32;
    const int E = in_sizes[1] / 2;
    const int G = out_size / 2;

    const int T = 256;
    const int nb = (N + SCAN_B - 1) / SCAN_B;   // <= NB_MAX, all resident
    const int e4 = (E + 3) / 4;
    const int scatB = (e4 + T - 1) / T;
    const int gemm1B = 296;
    const int work_blocks = 592;
    const int agg_blocks = 888;                  // 1 CTA wave, persistent

    // --- CSR build; scatter and gemm1 overlap in one launch (3 launches) ---
    hist_kernel<<<(e4 + T - 1) / T, T>>>(ei, E);
    scan_kernel<<<nb, SCAN_B>>>(N, nb);
    scatter_gemm1_kernel<<<scatB + gemm1B, T>>>(ei, E, x, W1, N, scatB);

    // --- Layers (5 launches) ---
    aggregate_kernel<<<agg_blocks, T>>>(b1, N);
    gemm64_kernel<<<work_blocks, T>>>(W2, N);
    aggregate_kernel<<<agg_blocks, T>>>(b2, N);
    gemm64_kernel<<<work_blocks, T>>>(W3, N);
    aggregate_kernel<<<agg_blocks, T>>>(b3, N);

    // --- Fused pool + MLP head (1 launch) ---
    pool_mlp_kernel<<<(G * 32 + T - 1) / T, T>>>(batch, lw1, lb1, lw2, lb2,
                                                 out, N, G);
}

// round 16
// speedup vs baseline: 1.0215x; 1.0215x over previous
#include <cuda_runtime.h>
#include <cuda_fp16.h>
#include <cuda_bf16.h>

// GCN: 3x (h = relu(A_norm @ (h @ W) + b)) -> global mean pool -> MLP.
// ALGEBRA: out[d] = dinv[d] * ( sum_e hhat[src_e] + hhat[d] ),
//          hhat[r] = dinv[r] * (h @ W)[r]  (prescaled in GEMM epilogue)
// -> no per-edge norms; scatter stores only 4B src indices.
// ALL intermediate tensors fp16 (hhat and activations h): halves aggregate
// write bytes, gemm64/pool read bytes. fp32 accumulation everywhere.
// 9 launches: hist(+rank), scan(spin-fused), scatter+gemm1(fused ranges),
// agg1, gemm2, agg2, gemm3, agg3, pool+mlp. No float atomics anywhere.
// Aggregate = R14's empirical winner: warp-per-node, 4-deep unroll, 6250 blks.

#define NMAX 50000
#define EMAX 800000
#define SCAN_B 1024
#define NB_MAX 64

__device__ __half2 g_hW16[NMAX * 32];  // dinv-prescaled GEMM out (agg input)
__device__ __half2 g_hA[NMAX * 32];    // activations fp16 (agg out, GEMM in)
__device__ float   g_dinv[NMAX];
__device__ int     g_deg[NMAX];        // re-zeroed every run
__device__ int     g_rowptr[NMAX + 1];
__device__ int     g_rank[EMAX];       // per-edge rank from hist
__device__ int     g_esrc[EMAX];       // CSR edge sources (4B records)
__device__ int     g_bsum[NB_MAX];
__device__ int     g_tick1, g_tick2;   // scan tickets (self-resetting)

// ---------------------------------------------------------------------------
// Histogram of dst; atomic return value = edge rank (stored coalesced).
__global__ void hist_kernel(const int* __restrict__ ei, int E) {
    int base = (blockIdx.x * blockDim.x + threadIdx.x) * 4;
    if ((E & 3) == 0) {
        if (base < E) {
            int4 d = *reinterpret_cast<const int4*>(ei + E + base);
            int4 r;
            r.x = atomicAdd(&g_deg[d.x], 1);
            r.y = atomicAdd(&g_deg[d.y], 1);
            r.z = atomicAdd(&g_deg[d.z], 1);
            r.w = atomicAdd(&g_deg[d.w], 1);
            *reinterpret_cast<int4*>(g_rank + base) = r;
        }
    } else {
#pragma unroll
        for (int j = 0; j < 4; j++)
            if (base + j < E)
                g_rank[base + j] = atomicAdd(&g_deg[ei[E + base + j]], 1);
    }
}

// Spin-fused scan (all nb<=49 blocks resident): reduce -> spin -> prefix ->
// rowptr/dinv, zero deg. Tickets self-reset for graph replay.
__global__ void scan_kernel(int n, int nb) {
    __shared__ int ws[32];
    __shared__ int blockoff;
    const int lane = threadIdx.x & 31, wid = threadIdx.x >> 5;
    int idx = blockIdx.x * SCAN_B + threadIdx.x;
    int v = (idx < n) ? g_deg[idx] : 0;
    int sc = v;
#pragma unroll
    for (int off = 1; off < 32; off <<= 1) {
        int u = __shfl_up_sync(0xffffffffu, sc, off);
        if (lane >= off) sc += u;
    }
    if (lane == 31) ws[wid] = sc;
    __syncthreads();
    if (wid == 0) {
        int s = ws[lane];
#pragma unroll
        for (int off = 1; off < 32; off <<= 1) {
            int u = __shfl_up_sync(0xffffffffu, s, off);
            if (lane >= off) s += u;
        }
        ws[lane] = s;
    }
    __syncthreads();
    if (threadIdx.x == 0) {
        g_bsum[blockIdx.x] = ws[31];
        __threadfence();
        atomicAdd(&g_tick1, 1);
        while (*((volatile int*)&g_tick1) < nb) {}
        int run = 0;
        for (int j = 0; j < blockIdx.x; j++)
            run += ((volatile int*)g_bsum)[j];
        blockoff = run;
    }
    __syncthreads();
    int ex = blockoff + (wid ? ws[wid - 1] : 0) + sc - v;
    if (idx < n) {
        g_rowptr[idx] = ex;
        g_dinv[idx] = rsqrtf((float)(v + 1));   // +1 self loop
        g_deg[idx] = 0;
        if (idx == n - 1) g_rowptr[n] = ex + v;
    }
    __syncthreads();
    if (threadIdx.x == 0) {
        int t = atomicAdd(&g_tick2, 1);
        if (t == nb - 1) { g_tick1 = 0; g_tick2 = 0; __threadfence(); }
    }
}

// Fused: blocks [0,scatB) scatter (4B store, atomic-free); rest do layer-1
// GEMM with dinv prescale. Both depend only on scan; fully independent.
__global__ void scatter_gemm1_kernel(const int* __restrict__ ei, int E,
                                     const float* __restrict__ X,
                                     const float* __restrict__ W, int n,
                                     int scatB) {
    if (blockIdx.x < scatB) {
        int base = (blockIdx.x * blockDim.x + threadIdx.x) * 4;
        if ((E & 3) == 0) {
            if (base < E) {
                int4 s4 = *reinterpret_cast<const int4*>(ei + base);
                int4 d4 = *reinterpret_cast<const int4*>(ei + E + base);
                int4 r4 = *reinterpret_cast<const int4*>(g_rank + base);
                g_esrc[g_rowptr[d4.x] + r4.x] = s4.x;
                g_esrc[g_rowptr[d4.y] + r4.y] = s4.y;
                g_esrc[g_rowptr[d4.z] + r4.z] = s4.z;
                g_esrc[g_rowptr[d4.w] + r4.w] = s4.w;
            }
        } else {
#pragma unroll
            for (int j = 0; j < 4; j++) {
                if (base + j < E) {
                    int s = ei[base + j], d = ei[E + base + j];
                    g_esrc[g_rowptr[d] + g_rank[base + j]] = s;
                }
            }
        }
        return;
    }
    // --- gemm1: hhat = fp16(dinv[row] * (X @ W1)[row]) ---
    __shared__ float2 Ws[32 * 32];   // Ws[k*32+l] = (W[k][2l], W[k][2l+1])
    for (int i = threadIdx.x; i < 32 * 32; i += blockDim.x)
        Ws[i] = reinterpret_cast<const float2*>(W)[i];
    __syncthreads();
    const int lane = threadIdx.x & 31;
    const int warp = ((blockIdx.x - scatB) * blockDim.x + threadIdx.x) >> 5;
    const int nwarps = ((gridDim.x - scatB) * blockDim.x) >> 5;
    for (int row = warp; row < n; row += nwarps) {
        float x0 = X[(unsigned)row * 32u + lane];
        float ax = 0.f, ay = 0.f;
#pragma unroll
        for (int k = 0; k < 32; k++) {
            float xv = __shfl_sync(0xffffffffu, x0, k);
            float2 w = Ws[k * 32 + lane];
            ax += xv * w.x; ay += xv * w.y;
        }
        float dn = g_dinv[row];
        g_hW16[(unsigned)row * 32u + lane] =
            __floats2half2_rn(ax * dn, ay * dn);
    }
}

// ---------------------------------------------------------------------------
// Mid-layer GEMM: hhat = fp16(dinv[row] * (hA[row] @ W)). Warp-per-row;
// reads fp16 activations, accumulates fp32.
__global__ void gemm64_kernel(const float* __restrict__ W, int n) {
    __shared__ float2 Ws[64 * 32];
    for (int i = threadIdx.x; i < 64 * 32; i += blockDim.x)
        Ws[i] = reinterpret_cast<const float2*>(W)[i];
    __syncthreads();
    const int lane = threadIdx.x & 31;
    const int warp = (blockIdx.x * blockDim.x + threadIdx.x) >> 5;
    const int nwarps = (gridDim.x * blockDim.x) >> 5;
    for (int row = warp; row < n; row += nwarps) {
        float2 xr = __half22float2(g_hA[(unsigned)row * 32u + lane]);
        float ax = 0.f, ay = 0.f;
#pragma unroll
        for (int k = 0; k < 32; k++) {
            float xk0 = __shfl_sync(0xffffffffu, xr.x, k);
            float xk1 = __shfl_sync(0xffffffffu, xr.y, k);
            float2 w0 = Ws[(2 * k) * 32 + lane];
            float2 w1 = Ws[(2 * k + 1) * 32 + lane];
            ax += xk0 * w0.x + xk1 * w1.x;
            ay += xk0 * w0.y + xk1 * w1.y;
        }
        float dn = g_dinv[row];
        g_hW16[(unsigned)row * 32u + lane] =
            __floats2half2_rn(ax * dn, ay * dn);
    }
}

// ---------------------------------------------------------------------------
// Norm-free aggregation (R14 winner): warp-per-node, 4-deep unroll.
// acc = hhat[node] + sum_e hhat[src_e]; hA = fp16(relu(dinv*acc + b)).
__global__ void aggregate_kernel(const float* __restrict__ b, int n) {
    const int lane = threadIdx.x & 31;
    const int node = (blockIdx.x * blockDim.x + threadIdx.x) >> 5;
    if (node >= n) return;
    float2 sv = __half22float2(g_hW16[(unsigned)node * 32u + lane]);
    float ax = sv.x, ay = sv.y;
    int p = g_rowptr[node];
    const int e = g_rowptr[node + 1];
    const int m = p + ((e - p) & ~3);
    for (; p < m; p += 4) {
        int s0 = g_esrc[p],     s1 = g_esrc[p + 1];
        int s2 = g_esrc[p + 2], s3 = g_esrc[p + 3];
        float2 v0 = __half22float2(g_hW16[(unsigned)s0 * 32u + lane]);
        float2 v1 = __half22float2(g_hW16[(unsigned)s1 * 32u + lane]);
        float2 v2 = __half22float2(g_hW16[(unsigned)s2 * 32u + lane]);
        float2 v3 = __half22float2(g_hW16[(unsigned)s3 * 32u + lane]);
        ax += v0.x + v1.x + v2.x + v3.x;
        ay += v0.y + v1.y + v2.y + v3.y;
    }
    for (; p < e; p++) {
        float2 v = __half22float2(g_hW16[(unsigned)g_esrc[p] * 32u + lane]);
        ax += v.x; ay += v.y;
    }
    float dn = g_dinv[node];
    float2 bb = reinterpret_cast<const float2*>(b)[lane];
    g_hA[(unsigned)node * 32u + lane] =
        __floats2half2_rn(fmaxf(dn * ax + bb.x, 0.f),
                          fmaxf(dn * ay + bb.y, 0.f));
}

// ---------------------------------------------------------------------------
__device__ __forceinline__ int lbound(const int* __restrict__ a, int n, int v) {
    int lo = 0, hi = n;
    while (lo < hi) {
        int m = (lo + hi) >> 1;
        if (a[m] < v) lo = m + 1; else hi = m;
    }
    return lo;
}

// Fused mean-pool + MLP head. One warp per graph (batch ids sorted).
__global__ void pool_mlp_kernel(const int* __restrict__ batch,
                                const float* __restrict__ lw1,
                                const float* __restrict__ lb1,
                                const float* __restrict__ lw2,
                                const float* __restrict__ lb2,
                                float* __restrict__ out, int n, int G) {
    __shared__ float2 Ws[64 * 32];
    for (int i = threadIdx.x; i < 64 * 32; i += blockDim.x)
        Ws[i] = reinterpret_cast<const float2*>(lw1)[i];
    __syncthreads();
    const int lane = threadIdx.x & 31;
    const int g = (blockIdx.x * blockDim.x + threadIdx.x) >> 5;
    if (g >= G) return;
    int start = lbound(batch, n, g);
    int end   = lbound(batch, n, g + 1);
    float px = 0.f, py = 0.f;
    for (int i = start; i < end; i++) {
        float2 v = __half22float2(g_hA[(unsigned)i * 32u + lane]);
        px += v.x; py += v.y;
    }
    int cnt = end - start;
    float inv = 1.f / (float)(cnt > 0 ? cnt : 1);
    px *= inv; py *= inv;

    float2 lb = reinterpret_cast<const float2*>(lb1)[lane];
    float ax = lb.x, ay = lb.y;
#pragma unroll
    for (int k = 0; k < 32; k++) {
        float pk0 = __shfl_sync(0xffffffffu, px, k);
        float pk1 = __shfl_sync(0xffffffffu, py, k);
        float2 w0 = Ws[(2 * k) * 32 + lane];
        float2 w1 = Ws[(2 * k + 1) * 32 + lane];
        ax += pk0 * w0.x + pk1 * w1.x;
        ay += pk0 * w0.y + pk1 * w1.y;
    }
    ax = fmaxf(ax, 0.f);
    ay = fmaxf(ay, 0.f);
    float4 w2 = reinterpret_cast<const float4*>(lw2)[lane];
    float o0 = ax * w2.x + ay * w2.z;
    float o1 = ax * w2.y + ay * w2.w;
#pragma unroll
    for (int off = 16; off; off >>= 1) {
        o0 += __shfl_down_sync(0xffffffffu, o0, off);
        o1 += __shfl_down_sync(0xffffffffu, o1, off);
    }
    if (lane == 0) {
        out[g * 2 + 0] = o0 + lb2[0];
        out[g * 2 + 1] = o1 + lb2[1];
    }
}

// ---------------------------------------------------------------------------
extern "C" void kernel_launch(void* const* d_in, const int* in_sizes, int n_in,
                              void* d_out, int out_size) {
    const float* x     = (const float*)d_in[0];
    const int*   ei    = (const int*)d_in[1];    // int64 ref -> int32 device
    const int*   batch = (const int*)d_in[2];
    const float* W1 = (const float*)d_in[3];
    const float* b1 = (const float*)d_in[4];
    const float* W2 = (const float*)d_in[5];
    const float* b2 = (const float*)d_in[6];
    const float* W3 = (const float*)d_in[7];
    const float* b3 = (const float*)d_in[8];
    const float* lw1 = (const float*)d_in[9];
    const float* lb1 = (const float*)d_in[10];
    const float* lw2 = (const float*)d_in[11];
    const float* lb2 = (const float*)d_in[12];
    float* out = (float*)d_out;

    const int N = in_sizes[0] / 32;
    const int E = in_sizes[1] / 2;
    const int G = out_size / 2;

    const int T = 256;
    const int nb = (N + SCAN_B - 1) / SCAN_B;   // <= NB_MAX, all resident
    const int e4 = (E + 3) / 4;
    const int scatB = (e4 + T - 1) / T;
    const int gemm1B = 296;
    const int work_blocks = 592;
    const int agg_blocks = (N * 32 + T - 1) / T;

    // --- CSR build; scatter and gemm1 overlap in one launch (3 launches) ---
    hist_kernel<<<(e4 + T - 1) / T, T>>>(ei, E);
    scan_kernel<<<nb, SCAN_B>>>(N, nb);
    scatter_gemm1_kernel<<<scatB + gemm1B, T>>>(ei, E, x, W1, N, scatB);

    // --- Layers (5 launches) ---
    aggregate_kernel<<<agg_blocks, T>>>(b1, N);
    gemm64_kernel<<<work_blocks, T>>>(W2, N);
    aggregate_kernel<<<agg_blocks, T>>>(b2, N);
    gemm64_kernel<<<work_blocks, T>>>(W3, N);
    aggregate_kernel<<<agg_blocks, T>>>(b3, N);

    // --- Fused pool + MLP head (1 launch) ---
    pool_mlp_kernel<<<(G * 32 + T - 1) / T, T>>>(batch, lw1, lb1, lw2, lb2,
                                                 out, N, G);
}